// round 7
// baseline (speedup 1.0000x reference)
#include <cuda_runtime.h>
#include <cuda_bf16.h>
#include <math.h>

// Problem constants
#define B_      16
#define T_      4
#define D_      2048
#define H_      8
#define G_      4
#define GSZ_    2
#define HD_     256
#define BLOCK_  16
#define KPAD_   260          // padded K/V row (floats) to avoid bank conflicts
#define WINDOW_ 1024
#define NBLK_   257
#define NCHUNK  16
#define NQ      8            // GSZ_ * T_ queries per (b,g)
#define SCALE_  0.0625f      // 256^-0.5
#define EPS_    1e-6f

// -------- device scratch (no allocs allowed) --------
__device__ __align__(16) float g_q [B_*T_*H_*HD_];          // 131072
__device__ __align__(16) float g_k [B_*T_*G_*HD_];          // 65536
__device__ __align__(16) float g_v [B_*T_*G_*HD_];          // 65536
__device__ __align__(16) float g_o [B_*T_*H_*HD_];          // 131072
__device__ __align__(16) float g_po[B_*G_*NCHUNK*NQ*HD_];   // 2M floats
__device__ __align__(16) float g_pm[B_*G_*NCHUNK*NQ];
__device__ __align__(16) float g_pl[B_*G_*NCHUNK*NQ];

// -------- zero scratch + output (atomic accumulation targets) --------
__global__ void zero_kernel(float* __restrict__ out) {
    int i = blockIdx.x * 256 + threadIdx.x;   // grid 512 -> i < 131072
    if (i < B_*T_*H_*HD_) g_q[i] = 0.f;
    if (i < B_*T_*G_*HD_) { g_k[i] = 0.f; g_v[i] = 0.f; }
    if (i < B_*T_*D_)     out[i] = 0.f;
}

// ==================== fused QKV GEMM ====================
__global__ __launch_bounds__(256)
void gemm_qkv(const float* __restrict__ x,
              const float* __restrict__ Wq,
              const float* __restrict__ Wk,
              const float* __restrict__ Wv) {
    const int K = D_;
    const int BK = 16;
    const int SPLITK = 8;

    int n0 = blockIdx.x * 64;          // virtual n in [0,4096)
    const float* Bm; float* C; int Nc; int nb;
    if (n0 < 2048)      { Bm = Wq + (long)n0 * K;          C = g_q; Nc = 2048; nb = n0; }
    else if (n0 < 3072) { Bm = Wk + (long)(n0 - 2048) * K; C = g_k; Nc = 1024; nb = n0 - 2048; }
    else                { Bm = Wv + (long)(n0 - 3072) * K; C = g_v; Nc = 1024; nb = n0 - 3072; }

    int kspan = K / SPLITK;            // 256
    int kbeg = blockIdx.y * kspan;
    int kend = kbeg + kspan;

    int tid = threadIdx.x;
    int tx = tid & 15, ty = tid >> 4;
    int lm = tid >> 2;                 // row 0..63
    int lk = (tid & 3) * 4;            // k offset

    __shared__ __align__(16) float As[BK][64 + 4];
    __shared__ __align__(16) float Bs[BK][64 + 4];

    const float* Ap = x  + (long)lm * K + lk;
    const float* Bp = Bm + (long)lm * K + lk;

    float acc[4][4] = {};

    float4 a4 = *reinterpret_cast<const float4*>(Ap + kbeg);
    float4 b4 = *reinterpret_cast<const float4*>(Bp + kbeg);

    for (int k0 = kbeg; k0 < kend; k0 += BK) {
        As[lk+0][lm] = a4.x; As[lk+1][lm] = a4.y; As[lk+2][lm] = a4.z; As[lk+3][lm] = a4.w;
        Bs[lk+0][lm] = b4.x; Bs[lk+1][lm] = b4.y; Bs[lk+2][lm] = b4.z; Bs[lk+3][lm] = b4.w;
        __syncthreads();
        if (k0 + BK < kend) {          // prefetch next tile while computing
            a4 = *reinterpret_cast<const float4*>(Ap + k0 + BK);
            b4 = *reinterpret_cast<const float4*>(Bp + k0 + BK);
        }
        #pragma unroll
        for (int k = 0; k < BK; ++k) {
            float4 av = *reinterpret_cast<const float4*>(&As[k][ty * 4]);
            float4 bv = *reinterpret_cast<const float4*>(&Bs[k][tx * 4]);
            acc[0][0] += av.x * bv.x; acc[0][1] += av.x * bv.y; acc[0][2] += av.x * bv.z; acc[0][3] += av.x * bv.w;
            acc[1][0] += av.y * bv.x; acc[1][1] += av.y * bv.y; acc[1][2] += av.y * bv.z; acc[1][3] += av.y * bv.w;
            acc[2][0] += av.z * bv.x; acc[2][1] += av.z * bv.y; acc[2][2] += av.z * bv.z; acc[2][3] += av.z * bv.w;
            acc[3][0] += av.w * bv.x; acc[3][1] += av.w * bv.y; acc[3][2] += av.w * bv.z; acc[3][3] += av.w * bv.w;
        }
        __syncthreads();
    }

    #pragma unroll
    for (int i = 0; i < 4; ++i)
        #pragma unroll
        for (int j = 0; j < 4; ++j)
            atomicAdd(&C[(long)(ty * 4 + i) * Nc + nb + tx * 4 + j], acc[i][j]);
}

// ==================== Wo GEMM: out[64,2048] += g_o[64,2048] * Wo[2048,2048]^T
__global__ __launch_bounds__(256)
void gemm_wo(const float* __restrict__ Wm, float* __restrict__ C) {
    const int K = H_ * HD_;            // 2048
    const int N = D_;                  // 2048
    const int BK = 16;
    const int SPLITK = 8;

    int n0 = blockIdx.x * 64;
    int kspan = K / SPLITK;
    int kbeg = blockIdx.y * kspan;
    int kend = kbeg + kspan;

    int tid = threadIdx.x;
    int tx = tid & 15, ty = tid >> 4;
    int lm = tid >> 2;
    int lk = (tid & 3) * 4;

    __shared__ __align__(16) float As[BK][64 + 4];
    __shared__ __align__(16) float Bs[BK][64 + 4];

    const float* Ap = g_o + (long)lm * K + lk;
    const float* Bp = Wm + (long)(n0 + lm) * K + lk;

    float acc[4][4] = {};

    float4 a4 = *reinterpret_cast<const float4*>(Ap + kbeg);
    float4 b4 = *reinterpret_cast<const float4*>(Bp + kbeg);

    for (int k0 = kbeg; k0 < kend; k0 += BK) {
        As[lk+0][lm] = a4.x; As[lk+1][lm] = a4.y; As[lk+2][lm] = a4.z; As[lk+3][lm] = a4.w;
        Bs[lk+0][lm] = b4.x; Bs[lk+1][lm] = b4.y; Bs[lk+2][lm] = b4.z; Bs[lk+3][lm] = b4.w;
        __syncthreads();
        if (k0 + BK < kend) {
            a4 = *reinterpret_cast<const float4*>(Ap + k0 + BK);
            b4 = *reinterpret_cast<const float4*>(Bp + k0 + BK);
        }
        #pragma unroll
        for (int k = 0; k < BK; ++k) {
            float4 av = *reinterpret_cast<const float4*>(&As[k][ty * 4]);
            float4 bv = *reinterpret_cast<const float4*>(&Bs[k][tx * 4]);
            acc[0][0] += av.x * bv.x; acc[0][1] += av.x * bv.y; acc[0][2] += av.x * bv.z; acc[0][3] += av.x * bv.w;
            acc[1][0] += av.y * bv.x; acc[1][1] += av.y * bv.y; acc[1][2] += av.y * bv.z; acc[1][3] += av.y * bv.w;
            acc[2][0] += av.z * bv.x; acc[2][1] += av.z * bv.y; acc[2][2] += av.z * bv.z; acc[2][3] += av.z * bv.w;
            acc[3][0] += av.w * bv.x; acc[3][1] += av.w * bv.y; acc[3][2] += av.w * bv.z; acc[3][3] += av.w * bv.w;
        }
        __syncthreads();
    }

    #pragma unroll
    for (int i = 0; i < 4; ++i)
        #pragma unroll
        for (int j = 0; j < 4; ++j)
            atomicAdd(&C[(long)(ty * 4 + i) * N + n0 + tx * 4 + j], acc[i][j]);
}

// -------- RMSNorm + RoPE on q and k rows (in place) --------
__global__ __launch_bounds__(256)
void normrope_kernel(const float* __restrict__ qns, const float* __restrict__ kns,
                     const int* __restrict__ kv_lens) {
    int r = blockIdx.x;
    int d = threadIdx.x;

    float* ptr; const float* sc; int b, t;
    if (r < B_*T_*H_) {
        ptr = g_q + (long)r * HD_; sc = qns;
        b = r / (T_ * H_); t = (r / H_) % T_;
    } else {
        int rk = r - B_*T_*H_;
        ptr = g_k + (long)rk * HD_; sc = kns;
        b = rk / (T_ * G_); t = (rk / G_) % T_;
    }

    float v = ptr[d];
    float ss = v * v;
    #pragma unroll
    for (int off = 16; off; off >>= 1) ss += __shfl_xor_sync(0xffffffffu, ss, off);
    __shared__ float red[8];
    if ((d & 31) == 0) red[d >> 5] = ss;
    __syncthreads();
    float tot = 0.f;
    #pragma unroll
    for (int w = 0; w < 8; ++w) tot += red[w];

    float rms = rsqrtf(tot / (float)HD_ + EPS_);
    float y = v * rms * (1.f + sc[d]);

    __shared__ float yb[HD_];
    yb[d] = y;
    __syncthreads();

    if (d < 128) {
        int pos = kv_lens[b] + t;
        float inv = exp2f(-(float)d * (13.287712379549449f / 128.f));
        float ang = (float)pos * inv;
        float sn, cs;
        sincosf(ang, &sn, &cs);
        float x1 = yb[d], x2 = yb[d + 128];
        ptr[d]       = x1 * cs - x2 * sn;
        ptr[d + 128] = x2 * cs + x1 * sn;
    }
}

// -------- split-window flash attention (partials) --------
// grid: (NCHUNK, G_, B_) = 1024 blocks, 256 threads.
// Score phase: lane = (key, dim-half) pair. After the pair-combine shuffle,
// the {2,4,8,16} butterfly stays within one parity class, so psum counts each
// key exactly ONCE (round-6 bug: erroneously halved it).
__global__ __launch_bounds__(256, 3)
void attn_kernel(const float* __restrict__ k_blocks, const float* __restrict__ v_blocks,
                 const int* __restrict__ block_tables, const int* __restrict__ kv_lens) {
    int c = blockIdx.x, g = blockIdx.y, b = blockIdx.z;
    int tid = threadIdx.x;
    int lane = tid & 31, warp = tid >> 5;

    __shared__ __align__(16) float Qs[NQ][HD_];
    __shared__ __align__(16) float Ks[BLOCK_][KPAD_];
    __shared__ __align__(16) float Vs[BLOCK_][KPAD_];
    __shared__ __align__(16) float Ps[BLOCK_][NQ];
    __shared__ float Al[NQ];

    int kvlen = kv_lens[b];
    int lo = max(0, kvlen - (WINDOW_ - 1));
    int hi = kvlen + T_ - 1;
    int L  = hi - lo + 1;
    int clen = (L + NCHUNK - 1) / NCHUNK;
    int cbeg = lo + c * clen;
    int cend = min(cbeg + clen, hi + 1);

    // load all 8 query vectors
    for (int e = tid; e < NQ * HD_; e += 256) {
        int qi = e >> 8, d = e & 255;
        int hl = qi >> 2, t = qi & 3;
        Qs[qi][d] = g_q[(((b * T_ + t) * H_) + g * GSZ_ + hl) * HD_ + d];
    }

    float acc[NQ];
    #pragma unroll
    for (int i = 0; i < NQ; ++i) acc[i] = 0.f;

    int qi_w  = warp;
    int t_w   = qi_w & 3;
    int pos_w = kvlen + t_w;
    float m_run = -INFINITY, l_run = 0.f;

    int hh = lane & 1;          // dim half (0: dims 0..127, 1: 128..255)
    int kk = lane >> 1;         // key index 0..15

    int jrow = tid >> 6;        // loader: base row 0..3
    int d4   = tid & 63;        // float4 index within row

    float4 kreg[4], vreg[4];

    auto load_tile = [&](int tbeg, int tn) {
        #pragma unroll
        for (int i = 0; i < 4; ++i) {
            int j  = jrow + i * 4;
            int jp = tbeg + j;
            float4 kz = make_float4(0.f,0.f,0.f,0.f), vz = kz;
            if (j < tn) {
                const float *kp, *vp;
                if (jp >= kvlen) {
                    int t = min(jp - kvlen, T_ - 1);
                    kp = &g_k[((b * T_ + t) * G_ + g) * HD_];
                    vp = &g_v[((b * T_ + t) * G_ + g) * HD_];
                } else {
                    int blk = block_tables[b * NBLK_ + (jp >> 4)];
                    long off = (((long)blk * G_ + g) * BLOCK_ + (jp & 15)) * (long)HD_;
                    kp = k_blocks + off;
                    vp = v_blocks + off;
                }
                kz = reinterpret_cast<const float4*>(kp)[d4];
                vz = reinterpret_cast<const float4*>(vp)[d4];
            }
            kreg[i] = kz; vreg[i] = vz;
        }
    };

    __syncthreads();   // Qs ready

    if (cbeg < cend) load_tile(cbeg, min(BLOCK_, cend - cbeg));

    for (int tbeg = cbeg; tbeg < cend; tbeg += BLOCK_) {
        int tn = min(BLOCK_, cend - tbeg);

        // commit prefetched tile to smem
        #pragma unroll
        for (int i = 0; i < 4; ++i) {
            int j = jrow + i * 4;
            reinterpret_cast<float4*>(&Ks[j][0])[d4] = kreg[i];
            reinterpret_cast<float4*>(&Vs[j][0])[d4] = vreg[i];
        }
        __syncthreads();

        // issue next tile's loads (overlap with compute below)
        int nbeg = tbeg + BLOCK_;
        if (nbeg < cend) load_tile(nbeg, min(BLOCK_, cend - nbeg));

        // scores: lane handles (key kk, half hh); 128-dim partial dot
        {
            const float4* q4 = reinterpret_cast<const float4*>(&Qs[qi_w][0]) + hh * 32;
            const float4* k4 = reinterpret_cast<const float4*>(&Ks[kk][0]) + hh * 32;
            float part = 0.f;
            #pragma unroll
            for (int i = 0; i < 32; ++i) {
                float4 qa = q4[i], kb2 = k4[i];
                part += qa.x * kb2.x + qa.y * kb2.y + qa.z * kb2.z + qa.w * kb2.w;
            }
            part += __shfl_xor_sync(0xffffffffu, part, 1);   // combine halves

            int jp = tbeg + kk;
            bool valid = (kk < tn) && (jp <= pos_w) && (jp > pos_w - WINDOW_);
            float s = valid ? part * SCALE_ : -INFINITY;

            float tmax = s;
            #pragma unroll
            for (int off = 2; off < 32; off <<= 1)
                tmax = fmaxf(tmax, __shfl_xor_sync(0xffffffffu, tmax, off));

            float alpha;
            if (tmax == -INFINITY) {                  // tile fully masked for q
                alpha = 1.f;
                if (hh == 0) Ps[kk][qi_w] = 0.f;
            } else {
                float m_new = fmaxf(m_run, tmax);
                alpha = __expf(m_run - m_new);        // m_run=-inf -> 0
                float p = __expf(s - m_new);          // s=-inf -> 0
                float psum = p;
                #pragma unroll
                for (int off = 2; off < 32; off <<= 1)
                    psum += __shfl_xor_sync(0xffffffffu, psum, off);
                l_run = l_run * alpha + psum;         // each key counted once
                m_run = m_new;
                if (hh == 0) Ps[kk][qi_w] = p;
            }
            if (lane == 0) Al[qi_w] = alpha;
        }
        __syncthreads();

        // accumulate P*V: thread owns dim d = tid for all 8 queries
        {
            int d = tid;
            #pragma unroll
            for (int q = 0; q < NQ; ++q) acc[q] *= Al[q];
            #pragma unroll
            for (int j = 0; j < BLOCK_; ++j) {
                float v = Vs[j][d];
                float4 p0 = *reinterpret_cast<const float4*>(&Ps[j][0]);
                float4 p1 = *reinterpret_cast<const float4*>(&Ps[j][4]);
                acc[0] += p0.x * v; acc[1] += p0.y * v; acc[2] += p0.z * v; acc[3] += p0.w * v;
                acc[4] += p1.x * v; acc[5] += p1.y * v; acc[6] += p1.z * v; acc[7] += p1.w * v;
            }
        }
        __syncthreads();
    }

    // write partials
    int base = ((b * G_ + g) * NCHUNK + c) * NQ;
    if (lane == 0) { g_pm[base + qi_w] = m_run; g_pl[base + qi_w] = l_run; }
    #pragma unroll
    for (int q = 0; q < NQ; ++q)
        g_po[(long)(base + q) * HD_ + tid] = acc[q];
}

// -------- combine split-window partials -> g_o --------
__global__ __launch_bounds__(256)
void combine_kernel() {
    int bg = blockIdx.x;
    int b = bg / G_, g = bg % G_;
    int d = threadIdx.x;
    int base = (b * G_ + g) * NCHUNK * NQ;

    for (int q = 0; q < NQ; ++q) {
        float M = -INFINITY;
        #pragma unroll
        for (int c = 0; c < NCHUNK; ++c)
            M = fmaxf(M, g_pm[base + c * NQ + q]);
        float Lsum = 0.f, o = 0.f;
        #pragma unroll
        for (int c = 0; c < NCHUNK; ++c) {
            float w = __expf(g_pm[base + c * NQ + q] - M);   // -inf -> 0
            Lsum += g_pl[base + c * NQ + q] * w;
            o += g_po[(long)(base + c * NQ + q) * HD_ + d] * w;
        }
        int hl = q >> 2, t = q & 3;
        g_o[((b * T_ + t) * H_ + g * GSZ_ + hl) * HD_ + d] = o / Lsum;
    }
}

// -------- launcher --------
extern "C" void kernel_launch(void* const* d_in, const int* in_sizes, int n_in,
                              void* d_out, int out_size) {
    const float* x   = (const float*)d_in[0];
    const float* Wq  = (const float*)d_in[1];
    const float* Wk  = (const float*)d_in[2];
    const float* Wv  = (const float*)d_in[3];
    const float* Wo  = (const float*)d_in[4];
    const float* qns = (const float*)d_in[5];
    const float* kns = (const float*)d_in[6];
    const float* kb  = (const float*)d_in[7];
    const float* vb  = (const float*)d_in[8];
    const int*   bt  = (const int*)d_in[9];
    const int*   kvl = (const int*)d_in[10];
    float* out = (float*)d_out;

    zero_kernel<<<512, 256>>>(out);

    gemm_qkv<<<dim3(64, 8), 256>>>(x, Wq, Wk, Wv);      // 512 CTAs

    normrope_kernel<<<B_*T_*(H_ + G_), 256>>>(qns, kns, kvl);

    attn_kernel<<<dim3(NCHUNK, G_, B_), 256>>>(kb, vb, bt, kvl);   // 1024 CTAs
    combine_kernel<<<B_*G_, 256>>>();

    gemm_wo<<<dim3(32, 8), 256>>>(Wo, out);             // 256 CTAs
}

// round 12
// speedup vs baseline: 1.1038x; 1.1038x over previous
#include <cuda_runtime.h>
#include <cuda_bf16.h>
#include <math.h>

// Problem constants
#define B_      16
#define T_      4
#define D_      2048
#define H_      8
#define G_      4
#define GSZ_    2
#define HD_     256
#define BLOCK_  16
#define KPAD_   260          // padded K/V row (floats) to avoid bank conflicts
#define WINDOW_ 1024
#define NBLK_   257
#define NCHUNK  16
#define NQ      8            // GSZ_ * T_ queries per (b,g)
#define SCALE_  0.0625f      // 256^-0.5
#define EPS_    1e-6f

// -------- device scratch (no allocs allowed) --------
__device__ __align__(16) float g_q [B_*T_*H_*HD_];
__device__ __align__(16) float g_k [B_*T_*G_*HD_];
__device__ __align__(16) float g_v [B_*T_*G_*HD_];
__device__ __align__(16) float g_o [B_*T_*H_*HD_];
__device__ __align__(16) float g_po[B_*G_*NCHUNK*NQ*HD_];
__device__ __align__(16) float g_pm[B_*G_*NCHUNK*NQ];
__device__ __align__(16) float g_pl[B_*G_*NCHUNK*NQ];

// -------- zero scratch + output (atomic accumulation targets) --------
__global__ void zero_kernel(float* __restrict__ out) {
    int i = blockIdx.x * 256 + threadIdx.x;   // grid 512 -> i < 131072
    if (i < B_*T_*H_*HD_) g_q[i] = 0.f;
    if (i < B_*T_*G_*HD_) { g_k[i] = 0.f; g_v[i] = 0.f; }
    if (i < B_*T_*D_)     out[i] = 0.f;
}

// ==================== fused QKV GEMM ====================
// BM=64, BN=64, BK=32, double-buffered smem, 1 barrier/iter, split-K atomics.
#define GBK 32
__global__ __launch_bounds__(256, 4)
void gemm_qkv(const float* __restrict__ x,
              const float* __restrict__ Wq,
              const float* __restrict__ Wk,
              const float* __restrict__ Wv) {
    const int K = D_;
    const int SPLITK = 8;

    int n0 = blockIdx.x * 64;          // virtual n in [0,4096)
    const float* Bm; float* C; int Nc; int nb;
    if (n0 < 2048)      { Bm = Wq + (long)n0 * K;          C = g_q; Nc = 2048; nb = n0; }
    else if (n0 < 3072) { Bm = Wk + (long)(n0 - 2048) * K; C = g_k; Nc = 1024; nb = n0 - 2048; }
    else                { Bm = Wv + (long)(n0 - 3072) * K; C = g_v; Nc = 1024; nb = n0 - 3072; }

    int kspan = K / SPLITK;            // 256
    int kbeg = blockIdx.y * kspan;
    int kend = kbeg + kspan;

    int tid = threadIdx.x;
    int tx = tid & 15, ty = tid >> 4;
    int lm = tid >> 2;                 // row 0..63 (4 threads per row)
    int lq = (tid & 3) * 4;            // first float4 col; second at +16

    __shared__ __align__(16) float As[2][GBK][68];
    __shared__ __align__(16) float Bs[2][GBK][68];

    const float* Ap = x  + (long)lm * K;
    const float* Bp = Bm + (long)lm * K;

    float acc[4][4] = {};
    float4 a0, a1, b0, b1;

    auto fetch = [&](int k0) {
        a0 = *reinterpret_cast<const float4*>(Ap + k0 + lq);
        a1 = *reinterpret_cast<const float4*>(Ap + k0 + lq + 16);
        b0 = *reinterpret_cast<const float4*>(Bp + k0 + lq);
        b1 = *reinterpret_cast<const float4*>(Bp + k0 + lq + 16);
    };
    auto stage = [&](int buf) {
        As[buf][lq+0][lm] = a0.x; As[buf][lq+1][lm] = a0.y; As[buf][lq+2][lm] = a0.z; As[buf][lq+3][lm] = a0.w;
        As[buf][lq+16][lm] = a1.x; As[buf][lq+17][lm] = a1.y; As[buf][lq+18][lm] = a1.z; As[buf][lq+19][lm] = a1.w;
        Bs[buf][lq+0][lm] = b0.x; Bs[buf][lq+1][lm] = b0.y; Bs[buf][lq+2][lm] = b0.z; Bs[buf][lq+3][lm] = b0.w;
        Bs[buf][lq+16][lm] = b1.x; Bs[buf][lq+17][lm] = b1.y; Bs[buf][lq+18][lm] = b1.z; Bs[buf][lq+19][lm] = b1.w;
    };

    fetch(kbeg); stage(0);
    __syncthreads();

    int cur = 0;
    for (int k0 = kbeg; k0 < kend; k0 += GBK) {
        bool more = (k0 + GBK < kend);
        if (more) fetch(k0 + GBK);

        #pragma unroll
        for (int k = 0; k < GBK; ++k) {
            float4 av = *reinterpret_cast<const float4*>(&As[cur][k][ty * 4]);
            float4 bv = *reinterpret_cast<const float4*>(&Bs[cur][k][tx * 4]);
            acc[0][0] += av.x * bv.x; acc[0][1] += av.x * bv.y; acc[0][2] += av.x * bv.z; acc[0][3] += av.x * bv.w;
            acc[1][0] += av.y * bv.x; acc[1][1] += av.y * bv.y; acc[1][2] += av.y * bv.z; acc[1][3] += av.y * bv.w;
            acc[2][0] += av.z * bv.x; acc[2][1] += av.z * bv.y; acc[2][2] += av.z * bv.z; acc[2][3] += av.z * bv.w;
            acc[3][0] += av.w * bv.x; acc[3][1] += av.w * bv.y; acc[3][2] += av.w * bv.z; acc[3][3] += av.w * bv.w;
        }
        if (more) stage(cur ^ 1);     // writes the buffer nobody reads this iter
        __syncthreads();
        cur ^= 1;
    }

    #pragma unroll
    for (int i = 0; i < 4; ++i)
        #pragma unroll
        for (int j = 0; j < 4; ++j)
            atomicAdd(&C[(long)(ty * 4 + i) * Nc + nb + tx * 4 + j], acc[i][j]);
}

// ==================== Wo GEMM: out[64,2048] += g_o[64,2048] * Wo[2048,2048]^T
__global__ __launch_bounds__(256, 4)
void gemm_wo(const float* __restrict__ Wm, float* __restrict__ C) {
    const int K = H_ * HD_;            // 2048
    const int N = D_;                  // 2048
    const int SPLITK = 8;

    int n0 = blockIdx.x * 64;
    int kspan = K / SPLITK;
    int kbeg = blockIdx.y * kspan;
    int kend = kbeg + kspan;

    int tid = threadIdx.x;
    int tx = tid & 15, ty = tid >> 4;
    int lm = tid >> 2;
    int lq = (tid & 3) * 4;

    __shared__ __align__(16) float As[2][GBK][68];
    __shared__ __align__(16) float Bs[2][GBK][68];

    const float* Ap = g_o + (long)lm * K;
    const float* Bp = Wm + (long)(n0 + lm) * K;

    float acc[4][4] = {};
    float4 a0, a1, b0, b1;

    auto fetch = [&](int k0) {
        a0 = *reinterpret_cast<const float4*>(Ap + k0 + lq);
        a1 = *reinterpret_cast<const float4*>(Ap + k0 + lq + 16);
        b0 = *reinterpret_cast<const float4*>(Bp + k0 + lq);
        b1 = *reinterpret_cast<const float4*>(Bp + k0 + lq + 16);
    };
    auto stage = [&](int buf) {
        As[buf][lq+0][lm] = a0.x; As[buf][lq+1][lm] = a0.y; As[buf][lq+2][lm] = a0.z; As[buf][lq+3][lm] = a0.w;
        As[buf][lq+16][lm] = a1.x; As[buf][lq+17][lm] = a1.y; As[buf][lq+18][lm] = a1.z; As[buf][lq+19][lm] = a1.w;
        Bs[buf][lq+0][lm] = b0.x; Bs[buf][lq+1][lm] = b0.y; Bs[buf][lq+2][lm] = b0.z; Bs[buf][lq+3][lm] = b0.w;
        Bs[buf][lq+16][lm] = b1.x; Bs[buf][lq+17][lm] = b1.y; Bs[buf][lq+18][lm] = b1.z; Bs[buf][lq+19][lm] = b1.w;
    };

    fetch(kbeg); stage(0);
    __syncthreads();

    int cur = 0;
    for (int k0 = kbeg; k0 < kend; k0 += GBK) {
        bool more = (k0 + GBK < kend);
        if (more) fetch(k0 + GBK);

        #pragma unroll
        for (int k = 0; k < GBK; ++k) {
            float4 av = *reinterpret_cast<const float4*>(&As[cur][k][ty * 4]);
            float4 bv = *reinterpret_cast<const float4*>(&Bs[cur][k][tx * 4]);
            acc[0][0] += av.x * bv.x; acc[0][1] += av.x * bv.y; acc[0][2] += av.x * bv.z; acc[0][3] += av.x * bv.w;
            acc[1][0] += av.y * bv.x; acc[1][1] += av.y * bv.y; acc[1][2] += av.y * bv.z; acc[1][3] += av.y * bv.w;
            acc[2][0] += av.z * bv.x; acc[2][1] += av.z * bv.y; acc[2][2] += av.z * bv.z; acc[2][3] += av.z * bv.w;
            acc[3][0] += av.w * bv.x; acc[3][1] += av.w * bv.y; acc[3][2] += av.w * bv.z; acc[3][3] += av.w * bv.w;
        }
        if (more) stage(cur ^ 1);
        __syncthreads();
        cur ^= 1;
    }

    #pragma unroll
    for (int i = 0; i < 4; ++i)
        #pragma unroll
        for (int j = 0; j < 4; ++j)
            atomicAdd(&C[(long)(ty * 4 + i) * N + n0 + tx * 4 + j], acc[i][j]);
}

// -------- RMSNorm + RoPE on q and k rows (in place) --------
__global__ __launch_bounds__(256)
void normrope_kernel(const float* __restrict__ qns, const float* __restrict__ kns,
                     const int* __restrict__ kv_lens) {
    int r = blockIdx.x;
    int d = threadIdx.x;

    float* ptr; const float* sc; int b, t;
    if (r < B_*T_*H_) {
        ptr = g_q + (long)r * HD_; sc = qns;
        b = r / (T_ * H_); t = (r / H_) % T_;
    } else {
        int rk = r - B_*T_*H_;
        ptr = g_k + (long)rk * HD_; sc = kns;
        b = rk / (T_ * G_); t = (rk / G_) % T_;
    }

    float v = ptr[d];
    float ss = v * v;
    #pragma unroll
    for (int off = 16; off; off >>= 1) ss += __shfl_xor_sync(0xffffffffu, ss, off);
    __shared__ float red[8];
    if ((d & 31) == 0) red[d >> 5] = ss;
    __syncthreads();
    float tot = 0.f;
    #pragma unroll
    for (int w = 0; w < 8; ++w) tot += red[w];

    float rms = rsqrtf(tot / (float)HD_ + EPS_);
    float y = v * rms * (1.f + sc[d]);

    __shared__ float yb[HD_];
    yb[d] = y;
    __syncthreads();

    if (d < 128) {
        int pos = kv_lens[b] + t;
        float inv = exp2f(-(float)d * (13.287712379549449f / 128.f));
        float ang = (float)pos * inv;
        float sn, cs;
        sincosf(ang, &sn, &cs);
        float x1 = yb[d], x2 = yb[d + 128];
        ptr[d]       = x1 * cs - x2 * sn;
        ptr[d + 128] = x2 * cs + x1 * sn;
    }
}

// -------- split-window flash attention (partials) --------
// grid: (NCHUNK, G_, B_) = 1024 blocks, 256 threads.
// Score phase: warp w covers dim-half H=w>>2 for query PAIR t=w&3 (queries t
// and t+4 share keys and mask). Lane = (key kk, dim-quarter ss): reads 64 dims
// of K once, dots against BOTH queries -> K smem traffic halved, 4 independent
// FMA chains. Half-scores staged in ShA/ShB; warp pairs sync via named barrier.
__global__ __launch_bounds__(256, 3)
void attn_kernel(const float* __restrict__ k_blocks, const float* __restrict__ v_blocks,
                 const int* __restrict__ block_tables, const int* __restrict__ kv_lens) {
    int c = blockIdx.x, g = blockIdx.y, b = blockIdx.z;
    int tid = threadIdx.x;
    int lane = tid & 31, warp = tid >> 5;

    __shared__ __align__(16) float Qs[NQ][HD_];
    __shared__ __align__(16) float Ks[BLOCK_][KPAD_];
    __shared__ __align__(16) float Vs[BLOCK_][KPAD_];
    __shared__ __align__(16) float Ps[BLOCK_][NQ];
    __shared__ float ShA[2][64];   // [H][t*16+kk] half-scores, q = t   (hl=0)
    __shared__ float ShB[2][64];   // [H][t*16+kk] half-scores, q = t+4 (hl=1)
    __shared__ float Al[NQ];

    int kvlen = kv_lens[b];
    int lo = max(0, kvlen - (WINDOW_ - 1));
    int hi = kvlen + T_ - 1;
    int L  = hi - lo + 1;
    int clen = (L + NCHUNK - 1) / NCHUNK;
    int cbeg = lo + c * clen;
    int cend = min(cbeg + clen, hi + 1);

    // load all 8 query vectors
    for (int e = tid; e < NQ * HD_; e += 256) {
        int qi = e >> 8, d = e & 255;
        int hl = qi >> 2, t = qi & 3;
        Qs[qi][d] = g_q[(((b * T_ + t) * H_) + g * GSZ_ + hl) * HD_ + d];
    }

    float acc[NQ];
    #pragma unroll
    for (int i = 0; i < NQ; ++i) acc[i] = 0.f;

    int qi_w  = warp;                 // softmax/stat owner (unchanged layout)
    int tq    = warp & 3;             // shared token index of the query pair
    int Hh    = warp >> 2;            // dim half this warp scores
    int pos_w = kvlen + tq;
    float m_run = -INFINITY, l_run = 0.f;

    int kk = lane >> 1;               // key 0..15
    int ssq = lane & 1;               // dim quarter within half

    int jrow = tid >> 6;              // loader: base row 0..3
    int d4   = tid & 63;              // float4 index within row

    float4 kreg[4], vreg[4];

    auto load_tile = [&](int tbeg, int tn) {
        #pragma unroll
        for (int i = 0; i < 4; ++i) {
            int j  = jrow + i * 4;
            int jp = tbeg + j;
            float4 kz = make_float4(0.f,0.f,0.f,0.f), vz = kz;
            if (j < tn) {
                const float *kp, *vp;
                if (jp >= kvlen) {
                    int t = min(jp - kvlen, T_ - 1);
                    kp = &g_k[((b * T_ + t) * G_ + g) * HD_];
                    vp = &g_v[((b * T_ + t) * G_ + g) * HD_];
                } else {
                    int blk = block_tables[b * NBLK_ + (jp >> 4)];
                    long off = (((long)blk * G_ + g) * BLOCK_ + (jp & 15)) * (long)HD_;
                    kp = k_blocks + off;
                    vp = v_blocks + off;
                }
                kz = reinterpret_cast<const float4*>(kp)[d4];
                vz = reinterpret_cast<const float4*>(vp)[d4];
            }
            kreg[i] = kz; vreg[i] = vz;
        }
    };

    __syncthreads();   // Qs ready

    if (cbeg < cend) load_tile(cbeg, min(BLOCK_, cend - cbeg));

    for (int tbeg = cbeg; tbeg < cend; tbeg += BLOCK_) {
        int tn = min(BLOCK_, cend - tbeg);

        // commit prefetched tile to smem
        #pragma unroll
        for (int i = 0; i < 4; ++i) {
            int j = jrow + i * 4;
            reinterpret_cast<float4*>(&Ks[j][0])[d4] = kreg[i];
            reinterpret_cast<float4*>(&Vs[j][0])[d4] = vreg[i];
        }
        __syncthreads();

        // issue next tile's loads (overlap with compute below)
        int nbeg = tbeg + BLOCK_;
        if (nbeg < cend) load_tile(nbeg, min(BLOCK_, cend - nbeg));

        // ---- score phase: 64-dim partial dots for both queries of pair tq
        {
            int off4 = Hh * 32 + ssq * 16;   // float4 offset of this lane's quarter
            const float4* k4 = reinterpret_cast<const float4*>(&Ks[kk][0]) + off4;
            const float4* qa = reinterpret_cast<const float4*>(&Qs[tq][0]) + off4;      // q = tq
            const float4* qb = reinterpret_cast<const float4*>(&Qs[tq + 4][0]) + off4;  // q = tq+4
            float pa0 = 0.f, pa1 = 0.f, pb0 = 0.f, pb1 = 0.f;
            #pragma unroll
            for (int i = 0; i < 16; ++i) {
                float4 kv = k4[i], a = qa[i], bqv = qb[i];
                pa0 += a.x * kv.x + a.y * kv.y;
                pa1 += a.z * kv.z + a.w * kv.w;
                pb0 += bqv.x * kv.x + bqv.y * kv.y;
                pb1 += bqv.z * kv.z + bqv.w * kv.w;
            }
            float pa = pa0 + pa1, pb = pb0 + pb1;
            pa += __shfl_xor_sync(0xffffffffu, pa, 1);   // combine quarters
            pb += __shfl_xor_sync(0xffffffffu, pb, 1);
            if (ssq == 0) ShA[Hh][tq * 16 + kk] = pa;
            else          ShB[Hh][tq * 16 + kk] = pb;
        }
        // sync the two H-half warps of this query pair (64 threads)
        asm volatile("bar.sync %0, %1;" :: "r"(1 + tq), "r"(64) : "memory");

        // ---- softmax phase: warp w owns query w (reads both halves)
        {
            int kk2 = lane & 15;
            const float* Sv = (warp < 4) ? &ShA[0][0] : &ShB[0][0];
            float sraw = Sv[tq * 16 + kk2] + Sv[64 + tq * 16 + kk2];
            int jp = tbeg + kk2;
            bool valid = (kk2 < tn) && (jp <= pos_w) && (jp > pos_w - WINDOW_);
            float s = valid ? sraw * SCALE_ : -INFINITY;

            float tmax = s;
            #pragma unroll
            for (int off = 1; off < 16; off <<= 1)
                tmax = fmaxf(tmax, __shfl_xor_sync(0xffffffffu, tmax, off));

            float alpha;
            if (tmax == -INFINITY) {
                alpha = 1.f;
                if (lane < 16) Ps[kk2][qi_w] = 0.f;
            } else {
                float m_new = fmaxf(m_run, tmax);
                alpha = __expf(m_run - m_new);
                float p = __expf(s - m_new);
                float psum = p;
                #pragma unroll
                for (int off = 1; off < 16; off <<= 1)
                    psum += __shfl_xor_sync(0xffffffffu, psum, off);
                l_run = l_run * alpha + psum;
                m_run = m_new;
                if (lane < 16) Ps[kk2][qi_w] = p;
            }
            if (lane == 0) Al[qi_w] = alpha;
        }
        __syncthreads();

        // ---- accumulate P*V: thread owns dim d = tid for all 8 queries
        {
            int d = tid;
            #pragma unroll
            for (int q = 0; q < NQ; ++q) acc[q] *= Al[q];
            #pragma unroll
            for (int j = 0; j < BLOCK_; ++j) {
                float v = Vs[j][d];
                float4 p0 = *reinterpret_cast<const float4*>(&Ps[j][0]);
                float4 p1 = *reinterpret_cast<const float4*>(&Ps[j][4]);
                acc[0] += p0.x * v; acc[1] += p0.y * v; acc[2] += p0.z * v; acc[3] += p0.w * v;
                acc[4] += p1.x * v; acc[5] += p1.y * v; acc[6] += p1.z * v; acc[7] += p1.w * v;
            }
        }
        __syncthreads();
    }

    // write partials
    int base = ((b * G_ + g) * NCHUNK + c) * NQ;
    if (lane == 0) { g_pm[base + qi_w] = m_run; g_pl[base + qi_w] = l_run; }
    #pragma unroll
    for (int q = 0; q < NQ; ++q)
        g_po[(long)(base + q) * HD_ + tid] = acc[q];
}

// -------- combine split-window partials -> g_o --------
__global__ __launch_bounds__(256)
void combine_kernel() {
    int bg = blockIdx.x;
    int b = bg / G_, g = bg % G_;
    int d = threadIdx.x;
    int base = (b * G_ + g) * NCHUNK * NQ;

    for (int q = 0; q < NQ; ++q) {
        float M = -INFINITY;
        #pragma unroll
        for (int c = 0; c < NCHUNK; ++c)
            M = fmaxf(M, g_pm[base + c * NQ + q]);
        float Lsum = 0.f, o = 0.f;
        #pragma unroll
        for (int c = 0; c < NCHUNK; ++c) {
            float w = __expf(g_pm[base + c * NQ + q] - M);   // -inf -> 0
            Lsum += g_pl[base + c * NQ + q] * w;
            o += g_po[(long)(base + c * NQ + q) * HD_ + d] * w;
        }
        int hl = q >> 2, t = q & 3;
        g_o[((b * T_ + t) * H_ + g * GSZ_ + hl) * HD_ + d] = o / Lsum;
    }
}

// -------- launcher --------
extern "C" void kernel_launch(void* const* d_in, const int* in_sizes, int n_in,
                              void* d_out, int out_size) {
    const float* x   = (const float*)d_in[0];
    const float* Wq  = (const float*)d_in[1];
    const float* Wk  = (const float*)d_in[2];
    const float* Wv  = (const float*)d_in[3];
    const float* Wo  = (const float*)d_in[4];
    const float* qns = (const float*)d_in[5];
    const float* kns = (const float*)d_in[6];
    const float* kb  = (const float*)d_in[7];
    const float* vb  = (const float*)d_in[8];
    const int*   bt  = (const int*)d_in[9];
    const int*   kvl = (const int*)d_in[10];
    float* out = (float*)d_out;

    zero_kernel<<<512, 256>>>(out);

    gemm_qkv<<<dim3(64, 8), 256>>>(x, Wq, Wk, Wv);      // 512 CTAs

    normrope_kernel<<<B_*T_*(H_ + G_), 256>>>(qns, kns, kvl);

    attn_kernel<<<dim3(NCHUNK, G_, B_), 256>>>(kb, vb, bt, kvl);   // 1024 CTAs
    combine_kernel<<<B_*G_, 256>>>();

    gemm_wo<<<dim3(32, 8), 256>>>(Wo, out);             // 256 CTAs
}

// round 14
// speedup vs baseline: 1.2173x; 1.1029x over previous
#include <cuda_runtime.h>
#include <cuda_bf16.h>
#include <math.h>
#include <stdint.h>

// Problem constants
#define B_      16
#define T_      4
#define D_      2048
#define H_      8
#define G_      4
#define GSZ_    2
#define HD_     256
#define BLOCK_  16
#define KPAD_   260          // padded K/V row (floats); 1040B row = 16B aligned
#define WINDOW_ 1024
#define NBLK_   257
#define NCHUNK  8
#define NQ      8            // GSZ_ * T_ queries per (b,g)
#define SCALE_  0.0625f      // 256^-0.5
#define EPS_    1e-6f
#define STAGES  3

// dynamic smem layout (floats)
#define SM_QS    0                       // [NQ][HD_]            2048
#define SM_KS    (SM_QS + NQ*HD_)        // [STAGES][16][KPAD_] 12480
#define SM_VS    (SM_KS + STAGES*BLOCK_*KPAD_)
#define SM_PS    (SM_VS + STAGES*BLOCK_*KPAD_)   // [16][8]       128
#define SM_SHA   (SM_PS + BLOCK_*NQ)             // [2][64]       128
#define SM_SHB   (SM_SHA + 128)                  // [2][64]       128
#define SM_AL    (SM_SHB + 128)                  // [8]
#define SM_TOT   (SM_AL + 8)
#define SMEM_ATTN_BYTES (SM_TOT * 4)

// -------- device scratch (no allocs allowed) --------
__device__ __align__(16) float g_q [B_*T_*H_*HD_];
__device__ __align__(16) float g_k [B_*T_*G_*HD_];
__device__ __align__(16) float g_v [B_*T_*G_*HD_];
__device__ __align__(16) float g_o [B_*T_*H_*HD_];
__device__ __align__(16) float g_po[B_*G_*NCHUNK*NQ*HD_];
__device__ __align__(16) float g_pm[B_*G_*NCHUNK*NQ];
__device__ __align__(16) float g_pl[B_*G_*NCHUNK*NQ];

__device__ __forceinline__ void cp_async16(float* dst_smem, const float* src) {
    unsigned int d = (unsigned int)__cvta_generic_to_shared(dst_smem);
    asm volatile("cp.async.cg.shared.global [%0], [%1], 16;" :: "r"(d), "l"(src) : "memory");
}
#define CP_COMMIT() asm volatile("cp.async.commit_group;" ::: "memory")
#define CP_WAIT2()  asm volatile("cp.async.wait_group 2;" ::: "memory")

// -------- zero scratch + output (atomic accumulation targets) --------
__global__ void zero_kernel(float* __restrict__ out) {
    int i = blockIdx.x * 256 + threadIdx.x;   // grid 512 -> i < 131072
    if (i < B_*T_*H_*HD_) g_q[i] = 0.f;
    if (i < B_*T_*G_*HD_) { g_k[i] = 0.f; g_v[i] = 0.f; }
    if (i < B_*T_*D_)     out[i] = 0.f;
}

// ==================== fused QKV GEMM ====================
#define GBK 32
__global__ __launch_bounds__(256, 4)
void gemm_qkv(const float* __restrict__ x,
              const float* __restrict__ Wq,
              const float* __restrict__ Wk,
              const float* __restrict__ Wv) {
    const int K = D_;
    const int SPLITK = 8;

    int n0 = blockIdx.x * 64;          // virtual n in [0,4096)
    const float* Bm; float* C; int Nc; int nb;
    if (n0 < 2048)      { Bm = Wq + (long)n0 * K;          C = g_q; Nc = 2048; nb = n0; }
    else if (n0 < 3072) { Bm = Wk + (long)(n0 - 2048) * K; C = g_k; Nc = 1024; nb = n0 - 2048; }
    else                { Bm = Wv + (long)(n0 - 3072) * K; C = g_v; Nc = 1024; nb = n0 - 3072; }

    int kspan = K / SPLITK;
    int kbeg = blockIdx.y * kspan;
    int kend = kbeg + kspan;

    int tid = threadIdx.x;
    int tx = tid & 15, ty = tid >> 4;
    int lm = tid >> 2;
    int lq = (tid & 3) * 4;

    __shared__ __align__(16) float As[2][GBK][68];
    __shared__ __align__(16) float Bs[2][GBK][68];

    const float* Ap = x  + (long)lm * K;
    const float* Bp = Bm + (long)lm * K;

    float acc[4][4] = {};
    float4 a0, a1, b0, b1;

    auto fetch = [&](int k0) {
        a0 = *reinterpret_cast<const float4*>(Ap + k0 + lq);
        a1 = *reinterpret_cast<const float4*>(Ap + k0 + lq + 16);
        b0 = *reinterpret_cast<const float4*>(Bp + k0 + lq);
        b1 = *reinterpret_cast<const float4*>(Bp + k0 + lq + 16);
    };
    auto stage = [&](int buf) {
        As[buf][lq+0][lm] = a0.x; As[buf][lq+1][lm] = a0.y; As[buf][lq+2][lm] = a0.z; As[buf][lq+3][lm] = a0.w;
        As[buf][lq+16][lm] = a1.x; As[buf][lq+17][lm] = a1.y; As[buf][lq+18][lm] = a1.z; As[buf][lq+19][lm] = a1.w;
        Bs[buf][lq+0][lm] = b0.x; Bs[buf][lq+1][lm] = b0.y; Bs[buf][lq+2][lm] = b0.z; Bs[buf][lq+3][lm] = b0.w;
        Bs[buf][lq+16][lm] = b1.x; Bs[buf][lq+17][lm] = b1.y; Bs[buf][lq+18][lm] = b1.z; Bs[buf][lq+19][lm] = b1.w;
    };

    fetch(kbeg); stage(0);
    __syncthreads();

    int cur = 0;
    for (int k0 = kbeg; k0 < kend; k0 += GBK) {
        bool more = (k0 + GBK < kend);
        if (more) fetch(k0 + GBK);

        #pragma unroll
        for (int k = 0; k < GBK; ++k) {
            float4 av = *reinterpret_cast<const float4*>(&As[cur][k][ty * 4]);
            float4 bv = *reinterpret_cast<const float4*>(&Bs[cur][k][tx * 4]);
            acc[0][0] += av.x * bv.x; acc[0][1] += av.x * bv.y; acc[0][2] += av.x * bv.z; acc[0][3] += av.x * bv.w;
            acc[1][0] += av.y * bv.x; acc[1][1] += av.y * bv.y; acc[1][2] += av.y * bv.z; acc[1][3] += av.y * bv.w;
            acc[2][0] += av.z * bv.x; acc[2][1] += av.z * bv.y; acc[2][2] += av.z * bv.z; acc[2][3] += av.z * bv.w;
            acc[3][0] += av.w * bv.x; acc[3][1] += av.w * bv.y; acc[3][2] += av.w * bv.z; acc[3][3] += av.w * bv.w;
        }
        if (more) stage(cur ^ 1);
        __syncthreads();
        cur ^= 1;
    }

    #pragma unroll
    for (int i = 0; i < 4; ++i)
        #pragma unroll
        for (int j = 0; j < 4; ++j)
            atomicAdd(&C[(long)(ty * 4 + i) * Nc + nb + tx * 4 + j], acc[i][j]);
}

// ==================== Wo GEMM ====================
__global__ __launch_bounds__(256, 4)
void gemm_wo(const float* __restrict__ Wm, float* __restrict__ C) {
    const int K = H_ * HD_;
    const int N = D_;
    const int SPLITK = 8;

    int n0 = blockIdx.x * 64;
    int kspan = K / SPLITK;
    int kbeg = blockIdx.y * kspan;
    int kend = kbeg + kspan;

    int tid = threadIdx.x;
    int tx = tid & 15, ty = tid >> 4;
    int lm = tid >> 2;
    int lq = (tid & 3) * 4;

    __shared__ __align__(16) float As[2][GBK][68];
    __shared__ __align__(16) float Bs[2][GBK][68];

    const float* Ap = g_o + (long)lm * K;
    const float* Bp = Wm + (long)(n0 + lm) * K;

    float acc[4][4] = {};
    float4 a0, a1, b0, b1;

    auto fetch = [&](int k0) {
        a0 = *reinterpret_cast<const float4*>(Ap + k0 + lq);
        a1 = *reinterpret_cast<const float4*>(Ap + k0 + lq + 16);
        b0 = *reinterpret_cast<const float4*>(Bp + k0 + lq);
        b1 = *reinterpret_cast<const float4*>(Bp + k0 + lq + 16);
    };
    auto stage = [&](int buf) {
        As[buf][lq+0][lm] = a0.x; As[buf][lq+1][lm] = a0.y; As[buf][lq+2][lm] = a0.z; As[buf][lq+3][lm] = a0.w;
        As[buf][lq+16][lm] = a1.x; As[buf][lq+17][lm] = a1.y; As[buf][lq+18][lm] = a1.z; As[buf][lq+19][lm] = a1.w;
        Bs[buf][lq+0][lm] = b0.x; Bs[buf][lq+1][lm] = b0.y; Bs[buf][lq+2][lm] = b0.z; Bs[buf][lq+3][lm] = b0.w;
        Bs[buf][lq+16][lm] = b1.x; Bs[buf][lq+17][lm] = b1.y; Bs[buf][lq+18][lm] = b1.z; Bs[buf][lq+19][lm] = b1.w;
    };

    fetch(kbeg); stage(0);
    __syncthreads();

    int cur = 0;
    for (int k0 = kbeg; k0 < kend; k0 += GBK) {
        bool more = (k0 + GBK < kend);
        if (more) fetch(k0 + GBK);

        #pragma unroll
        for (int k = 0; k < GBK; ++k) {
            float4 av = *reinterpret_cast<const float4*>(&As[cur][k][ty * 4]);
            float4 bv = *reinterpret_cast<const float4*>(&Bs[cur][k][tx * 4]);
            acc[0][0] += av.x * bv.x; acc[0][1] += av.x * bv.y; acc[0][2] += av.x * bv.z; acc[0][3] += av.x * bv.w;
            acc[1][0] += av.y * bv.x; acc[1][1] += av.y * bv.y; acc[1][2] += av.y * bv.z; acc[1][3] += av.y * bv.w;
            acc[2][0] += av.z * bv.x; acc[2][1] += av.z * bv.y; acc[2][2] += av.z * bv.z; acc[2][3] += av.z * bv.w;
            acc[3][0] += av.w * bv.x; acc[3][1] += av.w * bv.y; acc[3][2] += av.w * bv.z; acc[3][3] += av.w * bv.w;
        }
        if (more) stage(cur ^ 1);
        __syncthreads();
        cur ^= 1;
    }

    #pragma unroll
    for (int i = 0; i < 4; ++i)
        #pragma unroll
        for (int j = 0; j < 4; ++j)
            atomicAdd(&C[(long)(ty * 4 + i) * N + n0 + tx * 4 + j], acc[i][j]);
}

// -------- RMSNorm + RoPE on q and k rows (in place) --------
__global__ __launch_bounds__(256)
void normrope_kernel(const float* __restrict__ qns, const float* __restrict__ kns,
                     const int* __restrict__ kv_lens) {
    int r = blockIdx.x;
    int d = threadIdx.x;

    float* ptr; const float* sc; int b, t;
    if (r < B_*T_*H_) {
        ptr = g_q + (long)r * HD_; sc = qns;
        b = r / (T_ * H_); t = (r / H_) % T_;
    } else {
        int rk = r - B_*T_*H_;
        ptr = g_k + (long)rk * HD_; sc = kns;
        b = rk / (T_ * G_); t = (rk / G_) % T_;
    }

    float v = ptr[d];
    float ss = v * v;
    #pragma unroll
    for (int off = 16; off; off >>= 1) ss += __shfl_xor_sync(0xffffffffu, ss, off);
    __shared__ float red[8];
    if ((d & 31) == 0) red[d >> 5] = ss;
    __syncthreads();
    float tot = 0.f;
    #pragma unroll
    for (int w = 0; w < 8; ++w) tot += red[w];

    float rms = rsqrtf(tot / (float)HD_ + EPS_);
    float y = v * rms * (1.f + sc[d]);

    __shared__ float yb[HD_];
    yb[d] = y;
    __syncthreads();

    if (d < 128) {
        int pos = kv_lens[b] + t;
        float inv = exp2f(-(float)d * (13.287712379549449f / 128.f));
        float ang = (float)pos * inv;
        float sn, cs;
        sincosf(ang, &sn, &cs);
        float x1 = yb[d], x2 = yb[d + 128];
        ptr[d]       = x1 * cs - x2 * sn;
        ptr[d + 128] = x2 * cs + x1 * sn;
    }
}

// -------- split-window flash attention (cp.async 3-stage pipeline) --------
// grid: (NCHUNK=8, G_, B_) = 512 blocks, 256 threads, ~110KB dynamic smem.
__global__ __launch_bounds__(256)
void attn_kernel(const float* __restrict__ k_blocks, const float* __restrict__ v_blocks,
                 const int* __restrict__ block_tables, const int* __restrict__ kv_lens) {
    extern __shared__ __align__(16) float sm[];
    float* Qs = sm + SM_QS;                    // [NQ][HD_]
    float* Ps = sm + SM_PS;                    // [16][8]
    float* ShA = sm + SM_SHA;                  // [2][64]
    float* ShB = sm + SM_SHB;                  // [2][64]
    float* Al = sm + SM_AL;                    // [8]

    int c = blockIdx.x, g = blockIdx.y, b = blockIdx.z;
    int tid = threadIdx.x;
    int lane = tid & 31, warp = tid >> 5;

    int kvlen = kv_lens[b];
    int lo = max(0, kvlen - (WINDOW_ - 1));
    int hi = kvlen + T_ - 1;
    int L  = hi - lo + 1;
    int clen = (L + NCHUNK - 1) / NCHUNK;
    int cbeg = lo + c * clen;
    int cend = min(cbeg + clen, hi + 1);
    int nt = (cend > cbeg) ? (cend - cbeg + BLOCK_ - 1) / BLOCK_ : 0;

    // load all 8 query vectors
    for (int e = tid; e < NQ * HD_; e += 256) {
        int qi = e >> 8, d = e & 255;
        int hl = qi >> 2, t = qi & 3;
        Qs[qi * HD_ + d] = g_q[(((b * T_ + t) * H_) + g * GSZ_ + hl) * HD_ + d];
    }

    float acc[NQ];
    #pragma unroll
    for (int i = 0; i < NQ; ++i) acc[i] = 0.f;

    int qi_w  = warp;
    int tq    = warp & 3;
    int Hh    = warp >> 2;
    int pos_w = kvlen + tq;
    float m_run = -INFINITY, l_run = 0.f;

    int kk = lane >> 1;
    int ssq = lane & 1;

    int jrow = tid >> 6;               // loader: base row 0..3
    int d4   = tid & 63;               // float4 index within row

    // issue one tile's cp.async loads into stage st
    auto issue_tile = [&](int ti, int st) {
        if (ti < nt) {
            int tbeg = cbeg + ti * BLOCK_;
            int tn = min(BLOCK_, cend - tbeg);
            float* Kst = sm + SM_KS + st * BLOCK_ * KPAD_;
            float* Vst = sm + SM_VS + st * BLOCK_ * KPAD_;
            #pragma unroll
            for (int i = 0; i < 4; ++i) {
                int j  = jrow + i * 4;
                int jp = tbeg + j;
                float* dk = Kst + j * KPAD_ + d4 * 4;
                float* dv = Vst + j * KPAD_ + d4 * 4;
                if (j < tn) {
                    const float *kp, *vp;
                    if (jp >= kvlen) {
                        int t = min(jp - kvlen, T_ - 1);
                        kp = &g_k[((b * T_ + t) * G_ + g) * HD_];
                        vp = &g_v[((b * T_ + t) * G_ + g) * HD_];
                    } else {
                        int blk = block_tables[b * NBLK_ + (jp >> 4)];
                        long off = (((long)blk * G_ + g) * BLOCK_ + (jp & 15)) * (long)HD_;
                        kp = k_blocks + off;
                        vp = v_blocks + off;
                    }
                    cp_async16(dk, kp + d4 * 4);
                    cp_async16(dv, vp + d4 * 4);
                } else {
                    *reinterpret_cast<float4*>(dk) = make_float4(0.f,0.f,0.f,0.f);
                    *reinterpret_cast<float4*>(dv) = make_float4(0.f,0.f,0.f,0.f);
                }
            }
        }
        CP_COMMIT();
    };

    __syncthreads();   // Qs ready (also orders smem reuse across phases)

    issue_tile(0, 0);
    issue_tile(1, 1);
    issue_tile(2, 2);

    for (int ti = 0; ti < nt; ++ti) {
        int st = ti % STAGES;
        int tbeg = cbeg + ti * BLOCK_;
        int tn = min(BLOCK_, cend - tbeg);
        const float* Kst = sm + SM_KS + st * BLOCK_ * KPAD_;
        const float* Vst = sm + SM_VS + st * BLOCK_ * KPAD_;

        CP_WAIT2();          // own groups: tile ti complete
        __syncthreads();     // all threads' data visible

        // ---- score phase: 64-dim partial dots for both queries of pair tq
        {
            int off4 = Hh * 32 + ssq * 16;
            const float4* k4 = reinterpret_cast<const float4*>(Kst + kk * KPAD_) + off4;
            const float4* qa = reinterpret_cast<const float4*>(Qs + tq * HD_) + off4;
            const float4* qb = reinterpret_cast<const float4*>(Qs + (tq + 4) * HD_) + off4;
            float pa0 = 0.f, pa1 = 0.f, pb0 = 0.f, pb1 = 0.f;
            #pragma unroll
            for (int i = 0; i < 16; ++i) {
                float4 kv = k4[i], a = qa[i], bqv = qb[i];
                pa0 += a.x * kv.x + a.y * kv.y;
                pa1 += a.z * kv.z + a.w * kv.w;
                pb0 += bqv.x * kv.x + bqv.y * kv.y;
                pb1 += bqv.z * kv.z + bqv.w * kv.w;
            }
            float pa = pa0 + pa1, pb = pb0 + pb1;
            pa += __shfl_xor_sync(0xffffffffu, pa, 1);
            pb += __shfl_xor_sync(0xffffffffu, pb, 1);
            if (ssq == 0) ShA[Hh * 64 + tq * 16 + kk] = pa;
            else          ShB[Hh * 64 + tq * 16 + kk] = pb;
        }
        asm volatile("bar.sync %0, %1;" :: "r"(1 + tq), "r"(64) : "memory");

        // ---- softmax phase: warp w owns query w
        {
            int kk2 = lane & 15;
            const float* Sv = (warp < 4) ? ShA : ShB;
            float sraw = Sv[tq * 16 + kk2] + Sv[64 + tq * 16 + kk2];
            int jp = tbeg + kk2;
            bool valid = (kk2 < tn) && (jp <= pos_w) && (jp > pos_w - WINDOW_);
            float s = valid ? sraw * SCALE_ : -INFINITY;

            float tmax = s;
            #pragma unroll
            for (int off = 1; off < 16; off <<= 1)
                tmax = fmaxf(tmax, __shfl_xor_sync(0xffffffffu, tmax, off));

            float alpha;
            if (tmax == -INFINITY) {
                alpha = 1.f;
                if (lane < 16) Ps[kk2 * NQ + qi_w] = 0.f;
            } else {
                float m_new = fmaxf(m_run, tmax);
                alpha = __expf(m_run - m_new);
                float p = __expf(s - m_new);
                float psum = p;
                #pragma unroll
                for (int off = 1; off < 16; off <<= 1)
                    psum += __shfl_xor_sync(0xffffffffu, psum, off);
                l_run = l_run * alpha + psum;
                m_run = m_new;
                if (lane < 16) Ps[kk2 * NQ + qi_w] = p;
            }
            if (lane == 0) Al[qi_w] = alpha;
        }
        __syncthreads();

        // ---- accumulate P*V: thread owns dim d = tid for all 8 queries
        {
            int d = tid;
            #pragma unroll
            for (int q = 0; q < NQ; ++q) acc[q] *= Al[q];
            #pragma unroll
            for (int j = 0; j < BLOCK_; ++j) {
                float v = Vst[j * KPAD_ + d];
                float4 p0 = *reinterpret_cast<const float4*>(&Ps[j * NQ + 0]);
                float4 p1 = *reinterpret_cast<const float4*>(&Ps[j * NQ + 4]);
                acc[0] += p0.x * v; acc[1] += p0.y * v; acc[2] += p0.z * v; acc[3] += p0.w * v;
                acc[4] += p1.x * v; acc[5] += p1.y * v; acc[6] += p1.z * v; acc[7] += p1.w * v;
            }
        }
        __syncthreads();     // done reading stage st

        issue_tile(ti + 3, st);
    }

    // write partials
    int base = ((b * G_ + g) * NCHUNK + c) * NQ;
    if (lane == 0) { g_pm[base + qi_w] = m_run; g_pl[base + qi_w] = l_run; }
    #pragma unroll
    for (int q = 0; q < NQ; ++q)
        g_po[(long)(base + q) * HD_ + tid] = acc[q];
}

// -------- combine split-window partials -> g_o (grid: (B*G, NQ)) --------
__global__ __launch_bounds__(256)
void combine_kernel() {
    int bg = blockIdx.x;
    int q  = blockIdx.y;
    int b = bg / G_, g = bg % G_;
    int d = threadIdx.x;
    int base = (b * G_ + g) * NCHUNK * NQ;

    float M = -INFINITY;
    #pragma unroll
    for (int c = 0; c < NCHUNK; ++c)
        M = fmaxf(M, g_pm[base + c * NQ + q]);
    float Lsum = 0.f, o = 0.f;
    #pragma unroll
    for (int c = 0; c < NCHUNK; ++c) {
        float w = __expf(g_pm[base + c * NQ + q] - M);   // -inf -> 0
        Lsum += g_pl[base + c * NQ + q] * w;
        o += g_po[(long)(base + c * NQ + q) * HD_ + d] * w;
    }
    int hl = q >> 2, t = q & 3;
    g_o[((b * T_ + t) * H_ + g * GSZ_ + hl) * HD_ + d] = o / Lsum;
}

// -------- launcher --------
extern "C" void kernel_launch(void* const* d_in, const int* in_sizes, int n_in,
                              void* d_out, int out_size) {
    const float* x   = (const float*)d_in[0];
    const float* Wq  = (const float*)d_in[1];
    const float* Wk  = (const float*)d_in[2];
    const float* Wv  = (const float*)d_in[3];
    const float* Wo  = (const float*)d_in[4];
    const float* qns = (const float*)d_in[5];
    const float* kns = (const float*)d_in[6];
    const float* kb  = (const float*)d_in[7];
    const float* vb  = (const float*)d_in[8];
    const int*   bt  = (const int*)d_in[9];
    const int*   kvl = (const int*)d_in[10];
    float* out = (float*)d_out;

    cudaFuncSetAttribute(attn_kernel, cudaFuncAttributeMaxDynamicSharedMemorySize,
                         SMEM_ATTN_BYTES);

    zero_kernel<<<512, 256>>>(out);

    gemm_qkv<<<dim3(64, 8), 256>>>(x, Wq, Wk, Wv);      // 512 CTAs

    normrope_kernel<<<B_*T_*(H_ + G_), 256>>>(qns, kns, kvl);

    attn_kernel<<<dim3(NCHUNK, G_, B_), 256, SMEM_ATTN_BYTES>>>(kb, vb, bt, kvl);
    combine_kernel<<<dim3(B_*G_, NQ), 256>>>();

    gemm_wo<<<dim3(32, 8), 256>>>(Wo, out);             // 256 CTAs
}

// round 15
// speedup vs baseline: 1.4388x; 1.1820x over previous
#include <cuda_runtime.h>
#include <cuda_bf16.h>
#include <math.h>
#include <stdint.h>

// Problem constants
#define B_      16
#define T_      4
#define D_      2048
#define H_      8
#define G_      4
#define GSZ_    2
#define HD_     256
#define BLOCK_  16
#define KPAD_   260          // padded K/V row (floats); 1040B row = 16B aligned
#define WINDOW_ 1024
#define NBLK_   257
#define NCHUNK  8
#define NQ      8            // GSZ_ * T_ queries per (b,g)
#define SCALE_  0.0625f     // 256^-0.5
#define EPS_    1e-6f
#define STAGES  3

// dynamic smem layout (floats)
#define SM_QS    0                       // [NQ][HD_]            2048
#define SM_KS    (SM_QS + NQ*HD_)        // [STAGES][16][KPAD_] 12480
#define SM_VS    (SM_KS + STAGES*BLOCK_*KPAD_)
#define SM_PS    (SM_VS + STAGES*BLOCK_*KPAD_)   // [16][8]       128
#define SM_SHA   (SM_PS + BLOCK_*NQ)             // [2][64]       128
#define SM_SHB   (SM_SHA + 128)                  // [2][64]       128
#define SM_AL    (SM_SHB + 128)                  // [8]
#define SM_TOT   (SM_AL + 8)
#define SMEM_ATTN_BYTES (SM_TOT * 4)

// -------- device scratch (no allocs allowed) --------
__device__ __align__(16) float g_q [B_*T_*H_*HD_];
__device__ __align__(16) float g_k [B_*T_*G_*HD_];
__device__ __align__(16) float g_v [B_*T_*G_*HD_];
__device__ __align__(16) float g_o [B_*T_*H_*HD_];
__device__ __align__(16) float g_po[B_*G_*NCHUNK*NQ*HD_];
__device__ __align__(16) float g_pm[B_*G_*NCHUNK*NQ];
__device__ __align__(16) float g_pl[B_*G_*NCHUNK*NQ];

__device__ __forceinline__ void cp_async16(float* dst_smem, const float* src) {
    unsigned int d = (unsigned int)__cvta_generic_to_shared(dst_smem);
    asm volatile("cp.async.cg.shared.global [%0], [%1], 16;" :: "r"(d), "l"(src) : "memory");
}
#define CP_COMMIT() asm volatile("cp.async.commit_group;" ::: "memory")
#define CP_WAIT2()  asm volatile("cp.async.wait_group 2;" ::: "memory")

// -------- zero scratch + output (atomic accumulation targets) --------
__global__ void zero_kernel(float* __restrict__ out) {
    int i = blockIdx.x * 256 + threadIdx.x;   // grid 512 -> i < 131072
    if (i < B_*T_*H_*HD_) g_q[i] = 0.f;
    if (i < B_*T_*G_*HD_) { g_k[i] = 0.f; g_v[i] = 0.f; }
    if (i < B_*T_*D_)     out[i] = 0.f;
}

// ==================== fused QKV GEMM ====================
#define GBK 32
__global__ __launch_bounds__(256, 4)
void gemm_qkv(const float* __restrict__ x,
              const float* __restrict__ Wq,
              const float* __restrict__ Wk,
              const float* __restrict__ Wv) {
    const int K = D_;
    const int SPLITK = 8;

    int n0 = blockIdx.x * 64;          // virtual n in [0,4096)
    const float* Bm; float* C; int Nc; int nb;
    if (n0 < 2048)      { Bm = Wq + (long)n0 * K;          C = g_q; Nc = 2048; nb = n0; }
    else if (n0 < 3072) { Bm = Wk + (long)(n0 - 2048) * K; C = g_k; Nc = 1024; nb = n0 - 2048; }
    else                { Bm = Wv + (long)(n0 - 3072) * K; C = g_v; Nc = 1024; nb = n0 - 3072; }

    int kspan = K / SPLITK;
    int kbeg = blockIdx.y * kspan;
    int kend = kbeg + kspan;

    int tid = threadIdx.x;
    int tx = tid & 15, ty = tid >> 4;
    int lm = tid >> 2;
    int lq = (tid & 3) * 4;

    __shared__ __align__(16) float As[2][GBK][68];
    __shared__ __align__(16) float Bs[2][GBK][68];

    const float* Ap = x  + (long)lm * K;
    const float* Bp = Bm + (long)lm * K;

    float acc[4][4] = {};
    float4 a0, a1, b0, b1;

    auto fetch = [&](int k0) {
        a0 = *reinterpret_cast<const float4*>(Ap + k0 + lq);
        a1 = *reinterpret_cast<const float4*>(Ap + k0 + lq + 16);
        b0 = *reinterpret_cast<const float4*>(Bp + k0 + lq);
        b1 = *reinterpret_cast<const float4*>(Bp + k0 + lq + 16);
    };
    auto stage = [&](int buf) {
        As[buf][lq+0][lm] = a0.x; As[buf][lq+1][lm] = a0.y; As[buf][lq+2][lm] = a0.z; As[buf][lq+3][lm] = a0.w;
        As[buf][lq+16][lm] = a1.x; As[buf][lq+17][lm] = a1.y; As[buf][lq+18][lm] = a1.z; As[buf][lq+19][lm] = a1.w;
        Bs[buf][lq+0][lm] = b0.x; Bs[buf][lq+1][lm] = b0.y; Bs[buf][lq+2][lm] = b0.z; Bs[buf][lq+3][lm] = b0.w;
        Bs[buf][lq+16][lm] = b1.x; Bs[buf][lq+17][lm] = b1.y; Bs[buf][lq+18][lm] = b1.z; Bs[buf][lq+19][lm] = b1.w;
    };

    fetch(kbeg); stage(0);
    __syncthreads();

    int cur = 0;
    for (int k0 = kbeg; k0 < kend; k0 += GBK) {
        bool more = (k0 + GBK < kend);
        if (more) fetch(k0 + GBK);

        #pragma unroll
        for (int k = 0; k < GBK; ++k) {
            float4 av = *reinterpret_cast<const float4*>(&As[cur][k][ty * 4]);
            float4 bv = *reinterpret_cast<const float4*>(&Bs[cur][k][tx * 4]);
            acc[0][0] += av.x * bv.x; acc[0][1] += av.x * bv.y; acc[0][2] += av.x * bv.z; acc[0][3] += av.x * bv.w;
            acc[1][0] += av.y * bv.x; acc[1][1] += av.y * bv.y; acc[1][2] += av.y * bv.z; acc[1][3] += av.y * bv.w;
            acc[2][0] += av.z * bv.x; acc[2][1] += av.z * bv.y; acc[2][2] += av.z * bv.z; acc[2][3] += av.z * bv.w;
            acc[3][0] += av.w * bv.x; acc[3][1] += av.w * bv.y; acc[3][2] += av.w * bv.z; acc[3][3] += av.w * bv.w;
        }
        if (more) stage(cur ^ 1);
        __syncthreads();
        cur ^= 1;
    }

    #pragma unroll
    for (int i = 0; i < 4; ++i)
        #pragma unroll
        for (int j = 0; j < 4; ++j)
            atomicAdd(&C[(long)(ty * 4 + i) * Nc + nb + tx * 4 + j], acc[i][j]);
}

// ==================== Wo GEMM ====================
__global__ __launch_bounds__(256, 4)
void gemm_wo(const float* __restrict__ Wm, float* __restrict__ C) {
    const int K = H_ * HD_;
    const int N = D_;
    const int SPLITK = 8;

    int n0 = blockIdx.x * 64;
    int kspan = K / SPLITK;
    int kbeg = blockIdx.y * kspan;
    int kend = kbeg + kspan;

    int tid = threadIdx.x;
    int tx = tid & 15, ty = tid >> 4;
    int lm = tid >> 2;
    int lq = (tid & 3) * 4;

    __shared__ __align__(16) float As[2][GBK][68];
    __shared__ __align__(16) float Bs[2][GBK][68];

    const float* Ap = g_o + (long)lm * K;
    const float* Bp = Wm + (long)(n0 + lm) * K;

    float acc[4][4] = {};
    float4 a0, a1, b0, b1;

    auto fetch = [&](int k0) {
        a0 = *reinterpret_cast<const float4*>(Ap + k0 + lq);
        a1 = *reinterpret_cast<const float4*>(Ap + k0 + lq + 16);
        b0 = *reinterpret_cast<const float4*>(Bp + k0 + lq);
        b1 = *reinterpret_cast<const float4*>(Bp + k0 + lq + 16);
    };
    auto stage = [&](int buf) {
        As[buf][lq+0][lm] = a0.x; As[buf][lq+1][lm] = a0.y; As[buf][lq+2][lm] = a0.z; As[buf][lq+3][lm] = a0.w;
        As[buf][lq+16][lm] = a1.x; As[buf][lq+17][lm] = a1.y; As[buf][lq+18][lm] = a1.z; As[buf][lq+19][lm] = a1.w;
        Bs[buf][lq+0][lm] = b0.x; Bs[buf][lq+1][lm] = b0.y; Bs[buf][lq+2][lm] = b0.z; Bs[buf][lq+3][lm] = b0.w;
        Bs[buf][lq+16][lm] = b1.x; Bs[buf][lq+17][lm] = b1.y; Bs[buf][lq+18][lm] = b1.z; Bs[buf][lq+19][lm] = b1.w;
    };

    fetch(kbeg); stage(0);
    __syncthreads();

    int cur = 0;
    for (int k0 = kbeg; k0 < kend; k0 += GBK) {
        bool more = (k0 + GBK < kend);
        if (more) fetch(k0 + GBK);

        #pragma unroll
        for (int k = 0; k < GBK; ++k) {
            float4 av = *reinterpret_cast<const float4*>(&As[cur][k][ty * 4]);
            float4 bv = *reinterpret_cast<const float4*>(&Bs[cur][k][tx * 4]);
            acc[0][0] += av.x * bv.x; acc[0][1] += av.x * bv.y; acc[0][2] += av.x * bv.z; acc[0][3] += av.x * bv.w;
            acc[1][0] += av.y * bv.x; acc[1][1] += av.y * bv.y; acc[1][2] += av.y * bv.z; acc[1][3] += av.y * bv.w;
            acc[2][0] += av.z * bv.x; acc[2][1] += av.z * bv.y; acc[2][2] += av.z * bv.z; acc[2][3] += av.z * bv.w;
            acc[3][0] += av.w * bv.x; acc[3][1] += av.w * bv.y; acc[3][2] += av.w * bv.z; acc[3][3] += av.w * bv.w;
        }
        if (more) stage(cur ^ 1);
        __syncthreads();
        cur ^= 1;
    }

    #pragma unroll
    for (int i = 0; i < 4; ++i)
        #pragma unroll
        for (int j = 0; j < 4; ++j)
            atomicAdd(&C[(long)(ty * 4 + i) * N + n0 + tx * 4 + j], acc[i][j]);
}

// -------- RMSNorm + RoPE on q and k rows (in place) --------
__global__ __launch_bounds__(256)
void normrope_kernel(const float* __restrict__ qns, const float* __restrict__ kns,
                     const int* __restrict__ kv_lens) {
    int r = blockIdx.x;
    int d = threadIdx.x;

    float* ptr; const float* sc; int b, t;
    if (r < B_*T_*H_) {
        ptr = g_q + (long)r * HD_; sc = qns;
        b = r / (T_ * H_); t = (r / H_) % T_;
    } else {
        int rk = r - B_*T_*H_;
        ptr = g_k + (long)rk * HD_; sc = kns;
        b = rk / (T_ * G_); t = (rk / G_) % T_;
    }

    float v = ptr[d];
    float ss = v * v;
    #pragma unroll
    for (int off = 16; off; off >>= 1) ss += __shfl_xor_sync(0xffffffffu, ss, off);
    __shared__ float red[8];
    if ((d & 31) == 0) red[d >> 5] = ss;
    __syncthreads();
    float tot = 0.f;
    #pragma unroll
    for (int w = 0; w < 8; ++w) tot += red[w];

    float rms = rsqrtf(tot / (float)HD_ + EPS_);
    float y = v * rms * (1.f + sc[d]);

    __shared__ float yb[HD_];
    yb[d] = y;
    __syncthreads();

    if (d < 128) {
        int pos = kv_lens[b] + t;
        float inv = exp2f(-(float)d * (13.287712379549449f / 128.f));
        float ang = (float)pos * inv;
        float sn, cs;
        sincosf(ang, &sn, &cs);
        float x1 = yb[d], x2 = yb[d + 128];
        ptr[d]       = x1 * cs - x2 * sn;
        ptr[d + 128] = x2 * cs + x1 * sn;
    }
}

// -------- split-window flash attention (cp.async pipeline + Q-in-registers) --
// grid: (NCHUNK=8, G_, B_) = 512 blocks, 256 threads, ~110KB dynamic smem.
// Score decomposition: warp w = (query pair tq=w&3, dim-half dh=w>>2).
// Lane = (dim-quarter dq=lane>>3, key-pair kp=lane&7 covering keys kp, kp+8).
// Q slice (32 dims x 2 queries = 16 float4) lives in REGISTERS across all
// tiles; K smem reads are bank-conflict-free (bank = key + 8*dq + i mod 32).
__global__ __launch_bounds__(256)
void attn_kernel(const float* __restrict__ k_blocks, const float* __restrict__ v_blocks,
                 const int* __restrict__ block_tables, const int* __restrict__ kv_lens) {
    extern __shared__ __align__(16) float sm[];
    float* Qs = sm + SM_QS;                    // [NQ][HD_]
    float* Ps = sm + SM_PS;                    // [16][8]
    float* ShA = sm + SM_SHA;                  // [2][64]
    float* ShB = sm + SM_SHB;                  // [2][64]
    float* Al = sm + SM_AL;                    // [8]

    int c = blockIdx.x, g = blockIdx.y, b = blockIdx.z;
    int tid = threadIdx.x;
    int lane = tid & 31, warp = tid >> 5;

    int kvlen = kv_lens[b];
    int lo = max(0, kvlen - (WINDOW_ - 1));
    int hi = kvlen + T_ - 1;
    int L  = hi - lo + 1;
    int clen = (L + NCHUNK - 1) / NCHUNK;
    int cbeg = lo + c * clen;
    int cend = min(cbeg + clen, hi + 1);
    int nt = (cend > cbeg) ? (cend - cbeg + BLOCK_ - 1) / BLOCK_ : 0;

    // load all 8 query vectors to smem
    for (int e = tid; e < NQ * HD_; e += 256) {
        int qi = e >> 8, d = e & 255;
        int hl = qi >> 2, t = qi & 3;
        Qs[qi * HD_ + d] = g_q[(((b * T_ + t) * H_) + g * GSZ_ + hl) * HD_ + d];
    }

    float acc[NQ];
    #pragma unroll
    for (int i = 0; i < NQ; ++i) acc[i] = 0.f;

    int qi_w  = warp;
    int tq    = warp & 3;
    int dh    = warp >> 2;            // dim half this warp scores
    int pos_w = kvlen + tq;
    float m_run = -INFINITY, l_run = 0.f;

    int dq = lane >> 3;               // dim quarter within half (0..3)
    int kp = lane & 7;                // key pair: keys kp, kp+8

    int jrow = tid >> 6;              // loader: base row 0..3
    int d4   = tid & 63;              // float4 index within row

    // issue one tile's cp.async loads into stage st
    auto issue_tile = [&](int ti, int st) {
        if (ti < nt) {
            int tbeg = cbeg + ti * BLOCK_;
            int tn = min(BLOCK_, cend - tbeg);
            float* Kst = sm + SM_KS + st * BLOCK_ * KPAD_;
            float* Vst = sm + SM_VS + st * BLOCK_ * KPAD_;
            #pragma unroll
            for (int i = 0; i < 4; ++i) {
                int j  = jrow + i * 4;
                int jp = tbeg + j;
                float* dk = Kst + j * KPAD_ + d4 * 4;
                float* dv = Vst + j * KPAD_ + d4 * 4;
                if (j < tn) {
                    const float *kpt, *vpt;
                    if (jp >= kvlen) {
                        int t = min(jp - kvlen, T_ - 1);
                        kpt = &g_k[((b * T_ + t) * G_ + g) * HD_];
                        vpt = &g_v[((b * T_ + t) * G_ + g) * HD_];
                    } else {
                        int blk = block_tables[b * NBLK_ + (jp >> 4)];
                        long off = (((long)blk * G_ + g) * BLOCK_ + (jp & 15)) * (long)HD_;
                        kpt = k_blocks + off;
                        vpt = v_blocks + off;
                    }
                    cp_async16(dk, kpt + d4 * 4);
                    cp_async16(dv, vpt + d4 * 4);
                } else {
                    *reinterpret_cast<float4*>(dk) = make_float4(0.f,0.f,0.f,0.f);
                    *reinterpret_cast<float4*>(dv) = make_float4(0.f,0.f,0.f,0.f);
                }
            }
        }
        CP_COMMIT();
    };

    __syncthreads();   // Qs ready

    issue_tile(0, 0);
    issue_tile(1, 1);
    issue_tile(2, 2);

    // hoist this lane's Q slice into registers (once, reused for all tiles):
    // dims [dh*128 + dq*32, +32) of queries tq and tq+4 -> 8+8 float4
    float4 qra[8], qrb[8];
    {
        const float4* qa = reinterpret_cast<const float4*>(Qs + tq * HD_) + dh * 32 + dq * 8;
        const float4* qb = reinterpret_cast<const float4*>(Qs + (tq + 4) * HD_) + dh * 32 + dq * 8;
        #pragma unroll
        for (int i = 0; i < 8; ++i) { qra[i] = qa[i]; qrb[i] = qb[i]; }
    }

    for (int ti = 0; ti < nt; ++ti) {
        int st = ti % STAGES;
        int tbeg = cbeg + ti * BLOCK_;
        int tn = min(BLOCK_, cend - tbeg);
        const float* Kst = sm + SM_KS + st * BLOCK_ * KPAD_;
        const float* Vst = sm + SM_VS + st * BLOCK_ * KPAD_;

        CP_WAIT2();          // own groups: tile ti complete
        __syncthreads();     // all threads' data visible

        // ---- score phase: keys kp & kp+8, dims [dh*128+dq*32, +32), 2 queries
        {
            const float4* k0 = reinterpret_cast<const float4*>(Kst + kp * KPAD_) + dh * 32 + dq * 8;
            const float4* k1 = reinterpret_cast<const float4*>(Kst + (kp + 8) * KPAD_) + dh * 32 + dq * 8;
            float a0 = 0.f, a1 = 0.f, b0 = 0.f, b1 = 0.f;
            #pragma unroll
            for (int i = 0; i < 8; ++i) {
                float4 kv0 = k0[i], kv1 = k1[i];
                float4 qa = qra[i], qb = qrb[i];
                a0 += qa.x * kv0.x + qa.y * kv0.y + qa.z * kv0.z + qa.w * kv0.w;
                a1 += qa.x * kv1.x + qa.y * kv1.y + qa.z * kv1.z + qa.w * kv1.w;
                b0 += qb.x * kv0.x + qb.y * kv0.y + qb.z * kv0.z + qb.w * kv0.w;
                b1 += qb.x * kv1.x + qb.y * kv1.y + qb.z * kv1.z + qb.w * kv1.w;
            }
            // reduce over dq (lanes stride 8)
            #pragma unroll
            for (int off = 8; off < 32; off <<= 1) {
                a0 += __shfl_xor_sync(0xffffffffu, a0, off);
                a1 += __shfl_xor_sync(0xffffffffu, a1, off);
                b0 += __shfl_xor_sync(0xffffffffu, b0, off);
                b1 += __shfl_xor_sync(0xffffffffu, b1, off);
            }
            if (lane < 8) {
                ShA[dh * 64 + tq * 16 + kp]     = a0;
                ShA[dh * 64 + tq * 16 + kp + 8] = a1;
                ShB[dh * 64 + tq * 16 + kp]     = b0;
                ShB[dh * 64 + tq * 16 + kp + 8] = b1;
            }
        }
        asm volatile("bar.sync %0, %1;" :: "r"(1 + tq), "r"(64) : "memory");

        // ---- softmax phase: warp w owns query w (sums the two dim-halves)
        {
            int kk2 = lane & 15;
            const float* Sv = (warp < 4) ? ShA : ShB;
            float sraw = Sv[tq * 16 + kk2] + Sv[64 + tq * 16 + kk2];
            int jp = tbeg + kk2;
            bool valid = (kk2 < tn) && (jp <= pos_w) && (jp > pos_w - WINDOW_);
            float s = valid ? sraw * SCALE_ : -INFINITY;

            float tmax = s;
            #pragma unroll
            for (int off = 1; off < 16; off <<= 1)
                tmax = fmaxf(tmax, __shfl_xor_sync(0xffffffffu, tmax, off));

            float alpha;
            if (tmax == -INFINITY) {
                alpha = 1.f;
                if (lane < 16) Ps[kk2 * NQ + qi_w] = 0.f;
            } else {
                float m_new = fmaxf(m_run, tmax);
                alpha = __expf(m_run - m_new);
                float p = __expf(s - m_new);
                float psum = p;
                #pragma unroll
                for (int off = 1; off < 16; off <<= 1)
                    psum += __shfl_xor_sync(0xffffffffu, psum, off);
                l_run = l_run * alpha + psum;
                m_run = m_new;
                if (lane < 16) Ps[kk2 * NQ + qi_w] = p;
            }
            if (lane == 0) Al[qi_w] = alpha;
        }
        __syncthreads();

        // ---- accumulate P*V: thread owns dim d = tid for all 8 queries
        {
            int d = tid;
            #pragma unroll
            for (int q = 0; q < NQ; ++q) acc[q] *= Al[q];
            #pragma unroll
            for (int j = 0; j < BLOCK_; ++j) {
                float v = Vst[j * KPAD_ + d];
                float4 p0 = *reinterpret_cast<const float4*>(&Ps[j * NQ + 0]);
                float4 p1 = *reinterpret_cast<const float4*>(&Ps[j * NQ + 4]);
                acc[0] += p0.x * v; acc[1] += p0.y * v; acc[2] += p0.z * v; acc[3] += p0.w * v;
                acc[4] += p1.x * v; acc[5] += p1.y * v; acc[6] += p1.z * v; acc[7] += p1.w * v;
            }
        }
        __syncthreads();     // done reading stage st

        issue_tile(ti + 3, st);
    }

    // write partials
    int base = ((b * G_ + g) * NCHUNK + c) * NQ;
    if (lane == 0) { g_pm[base + qi_w] = m_run; g_pl[base + qi_w] = l_run; }
    #pragma unroll
    for (int q = 0; q < NQ; ++q)
        g_po[(long)(base + q) * HD_ + tid] = acc[q];
}

// -------- combine split-window partials -> g_o (grid: (B*G, NQ)) --------
__global__ __launch_bounds__(256)
void combine_kernel() {
    int bg = blockIdx.x;
    int q  = blockIdx.y;
    int b = bg / G_, g = bg % G_;
    int d = threadIdx.x;
    int base = (b * G_ + g) * NCHUNK * NQ;

    float M = -INFINITY;
    #pragma unroll
    for (int c = 0; c < NCHUNK; ++c)
        M = fmaxf(M, g_pm[base + c * NQ + q]);
    float Lsum = 0.f, o = 0.f;
    #pragma unroll
    for (int c = 0; c < NCHUNK; ++c) {
        float w = __expf(g_pm[base + c * NQ + q] - M);   // -inf -> 0
        Lsum += g_pl[base + c * NQ + q] * w;
        o += g_po[(long)(base + c * NQ + q) * HD_ + d] * w;
    }
    int hl = q >> 2, t = q & 3;
    g_o[((b * T_ + t) * H_ + g * GSZ_ + hl) * HD_ + d] = o / Lsum;
}

// -------- launcher --------
extern "C" void kernel_launch(void* const* d_in, const int* in_sizes, int n_in,
                              void* d_out, int out_size) {
    const float* x   = (const float*)d_in[0];
    const float* Wq  = (const float*)d_in[1];
    const float* Wk  = (const float*)d_in[2];
    const float* Wv  = (const float*)d_in[3];
    const float* Wo  = (const float*)d_in[4];
    const float* qns = (const float*)d_in[5];
    const float* kns = (const float*)d_in[6];
    const float* kb  = (const float*)d_in[7];
    const float* vb  = (const float*)d_in[8];
    const int*   bt  = (const int*)d_in[9];
    const int*   kvl = (const int*)d_in[10];
    float* out = (float*)d_out;

    cudaFuncSetAttribute(attn_kernel, cudaFuncAttributeMaxDynamicSharedMemorySize,
                         SMEM_ATTN_BYTES);

    zero_kernel<<<512, 256>>>(out);

    gemm_qkv<<<dim3(64, 8), 256>>>(x, Wq, Wk, Wv);      // 512 CTAs

    normrope_kernel<<<B_*T_*(H_ + G_), 256>>>(qns, kns, kvl);

    attn_kernel<<<dim3(NCHUNK, G_, B_), 256, SMEM_ATTN_BYTES>>>(kb, vb, bt, kvl);
    combine_kernel<<<dim3(B_*G_, NQ), 256>>>();

    gemm_wo<<<dim3(32, 8), 256>>>(Wo, out);             // 256 CTAs
}